// round 2
// baseline (speedup 1.0000x reference)
#include <cuda_runtime.h>
#include <cuda_bf16.h>

// Problem constants
#define BB 8
#define NN 256
#define DD 64   // DIN = DOUT = EIN = EOUT = 64

typedef unsigned long long u64;

// Scratch (device globals — no allocation allowed)
__device__ float g_node_x[BB * NN * DD];   // emb_node @ Wn + bn
__device__ float g_sx_relu[BB * NN * DD];  // relu(emb_node @ Wsn + bsn)

// ---------------------------------------------------------------------------
// Kernel A: node GEMMs. One block (64 threads) per (b, j) row.
// ---------------------------------------------------------------------------
__global__ void node_gemm_kernel(const float* __restrict__ emb_node,
                                 const float* __restrict__ Wn,
                                 const float* __restrict__ bn,
                                 const float* __restrict__ Wsn,
                                 const float* __restrict__ bsn) {
    const int r = blockIdx.x;          // b*256 + j
    const int c = threadIdx.x;         // 0..63
    __shared__ float e[DD];
    e[c] = emb_node[r * DD + c];
    __syncthreads();
    float a1 = bn[c];
    float a2 = bsn[c];
#pragma unroll
    for (int k = 0; k < DD; k++) {
        const float ev = e[k];
        a1 = fmaf(ev, Wn[k * DD + c], a1);
        a2 = fmaf(ev, Wsn[k * DD + c], a2);
    }
    g_node_x[r * DD + c] = a1;
    g_sx_relu[r * DD + c] = fmaxf(a2, 0.0f);
}

// ---------------------------------------------------------------------------
// f32x2 helpers (packed fp32 pair math — exact fp32 numerics, 2x issue width)
// ---------------------------------------------------------------------------
__device__ __forceinline__ u64 pack2(float lo, float hi) {
    u64 r;
    asm("mov.b64 %0, {%1, %2};" : "=l"(r) : "f"(lo), "f"(hi));
    return r;
}
__device__ __forceinline__ u64 bcast2(float v) {
    u64 r;
    asm("mov.b64 %0, {%1, %1};" : "=l"(r) : "f"(v));
    return r;
}
__device__ __forceinline__ void fma2(u64& d, u64 a, u64 b) {
    asm("fma.rn.f32x2 %0, %1, %2, %0;" : "+l"(d) : "l"(a), "l"(b));
}
__device__ __forceinline__ void unpack2(u64 v, float& lo, float& hi) {
    asm("mov.b64 {%0, %1}, %2;" : "=f"(lo), "=f"(hi) : "l"(v));
}

// ---------------------------------------------------------------------------
// Kernel B: per (b,i): edge GEMM over all j (256x64 output tile), fused
// relu->edge_out, and masked channel-independent aggregation -> node_out.
// Block: 256 threads; thread (tx,ty) owns an 8j x 8c register tile.
// Inner loop uses packed fma.rn.f32x2 (channel pairs).
// Shared: E tile (256x64 f32), We (64x64), A row (256), reduction (32x64).
// ---------------------------------------------------------------------------
__global__ __launch_bounds__(256, 2)
void edge_agg_kernel(const float* __restrict__ A,
                     const float* __restrict__ emb_edge,
                     const float* __restrict__ We,
                     const float* __restrict__ be,
                     float* __restrict__ out) {
    const int i = blockIdx.x;   // 0..255
    const int b = blockIdx.y;   // 0..7
    const int tid = threadIdx.x;
    const int tx = tid & 7;     // c-group: c = tx*8 .. tx*8+7
    const int ty = tid >> 3;    // j-group: j = ty*8 .. ty*8+7

    extern __shared__ float sh[];
    float* Esh = sh;                    // 16384 floats
    float* Wsh = Esh + NN * DD;         // 4096 floats
    float* Ash = Wsh + DD * DD;         // 256 floats
    float* red = Ash + NN;              // 32*64 = 2048 floats

    const int bi = b * NN + i;

    // ---- stage inputs into shared ----
    {
        const float4* eg4 = (const float4*)(emb_edge + (size_t)bi * NN * DD);
        float4* E4 = (float4*)Esh;
#pragma unroll
        for (int t = 0; t < 16; t++) E4[tid + t * 256] = eg4[tid + t * 256];
        const float4* w4 = (const float4*)We;
        float4* W4 = (float4*)Wsh;
#pragma unroll
        for (int t = 0; t < 4; t++) W4[tid + t * 256] = w4[tid + t * 256];
        Ash[tid] = A[(size_t)bi * NN + tid];
    }
    __syncthreads();

    // ---- packed accumulators initialized with bias ----
    u64 acc[8][4];   // [jj][channel-pair q]: channels (tx*8+2q, tx*8+2q+1)
    {
        const float* bep = &be[tx * 8];
        u64 b0 = pack2(bep[0], bep[1]);
        u64 b1 = pack2(bep[2], bep[3]);
        u64 b2 = pack2(bep[4], bep[5]);
        u64 b3 = pack2(bep[6], bep[7]);
#pragma unroll
        for (int jj = 0; jj < 8; jj++) {
            acc[jj][0] = b0; acc[jj][1] = b1; acc[jj][2] = b2; acc[jj][3] = b3;
        }
    }

    // ---- main loop: edge_x tile = E(8j x 64k) @ We(64k x 8c), f32x2 packed ----
#pragma unroll 4
    for (int k = 0; k < DD; k += 4) {
        float4 e4[8];
#pragma unroll
        for (int jj = 0; jj < 8; jj++)
            e4[jj] = *(const float4*)&Esh[(ty * 8 + jj) * DD + k];
#pragma unroll
        for (int kk = 0; kk < 4; kk++) {
            const u64* wrow = (const u64*)&Wsh[(k + kk) * DD + tx * 8];
            const u64 w0 = wrow[0];
            const u64 w1 = wrow[1];
            const u64 w2 = wrow[2];
            const u64 w3 = wrow[3];
#pragma unroll
            for (int jj = 0; jj < 8; jj++) {
                const float ev = (kk == 0) ? e4[jj].x : (kk == 1) ? e4[jj].y
                               : (kk == 2) ? e4[jj].z : e4[jj].w;
                const u64 ev2 = bcast2(ev);
                fma2(acc[jj][0], ev2, w0);
                fma2(acc[jj][1], ev2, w1);
                fma2(acc[jj][2], ev2, w2);
                fma2(acc[jj][3], ev2, w3);
            }
        }
    }

    // ---- epilogue: edge_out = relu(edge_x); partial agg over this thread's j's ----
    float p[8];
#pragma unroll
    for (int cc = 0; cc < 8; cc++) p[cc] = 0.0f;

    const float* nx = g_node_x + (size_t)b * NN * DD;
    float* edge_out = out + BB * NN * DD + (size_t)bi * NN * DD;

#pragma unroll
    for (int jj = 0; jj < 8; jj++) {
        const int j = ty * 8 + jj;
        const float a = Ash[j];
        const float4 n0 = *(const float4*)&nx[j * DD + tx * 8];
        const float4 n1 = *(const float4*)&nx[j * DD + tx * 8 + 4];
        const float nvals[8] = {n0.x, n0.y, n0.z, n0.w, n1.x, n1.y, n1.z, n1.w};
        float v[8];
        unpack2(acc[jj][0], v[0], v[1]);
        unpack2(acc[jj][1], v[2], v[3]);
        unpack2(acc[jj][2], v[4], v[5]);
        unpack2(acc[jj][3], v[6], v[7]);
        float4 o0, o1;
        float* o0f = (float*)&o0;
        float* o1f = (float*)&o1;
#pragma unroll
        for (int cc = 0; cc < 8; cc++) {
            p[cc] = fmaf(a * v[cc], nvals[cc], p[cc]);
            const float rv = fmaxf(v[cc], 0.0f);
            if (cc < 4) o0f[cc] = rv; else o1f[cc - 4] = rv;
        }
        *(float4*)&edge_out[j * DD + tx * 8]     = o0;
        *(float4*)&edge_out[j * DD + tx * 8 + 4] = o1;
    }

    // ---- reduce partials over the 32 ty-groups ----
    *(float4*)&red[ty * DD + tx * 8]     = make_float4(p[0], p[1], p[2], p[3]);
    *(float4*)&red[ty * DD + tx * 8 + 4] = make_float4(p[4], p[5], p[6], p[7]);
    __syncthreads();

    if (tid < DD) {
        float s = 0.0f;
#pragma unroll
        for (int t = 0; t < 32; t++) s += red[t * DD + tid];
        out[(size_t)bi * DD + tid] = fmaxf(s, 0.0f) + g_sx_relu[(size_t)bi * DD + tid];
    }
}

// ---------------------------------------------------------------------------
// Launch
// ---------------------------------------------------------------------------
extern "C" void kernel_launch(void* const* d_in, const int* in_sizes, int n_in,
                              void* d_out, int out_size) {
    const float* A        = (const float*)d_in[0];   // [8,256,256]
    const float* emb_node = (const float*)d_in[1];   // [8,256,64]
    const float* emb_edge = (const float*)d_in[2];   // [8,256,256,64]
    const float* Wn       = (const float*)d_in[3];   // [64,64]
    const float* bn       = (const float*)d_in[4];   // [64]
    const float* Wsn      = (const float*)d_in[5];   // [64,64]
    const float* bsn      = (const float*)d_in[6];   // [64]
    const float* We       = (const float*)d_in[7];   // [64,64]
    const float* be       = (const float*)d_in[8];   // [64]
    float* out = (float*)d_out;                      // node_out [8,256,64] then edge_out [8,256,256,64]

    const int smem = (NN * DD + DD * DD + NN + 32 * DD) * sizeof(float); // 91136 B
    cudaFuncSetAttribute(edge_agg_kernel, cudaFuncAttributeMaxDynamicSharedMemorySize, smem);

    node_gemm_kernel<<<BB * NN, DD>>>(emb_node, Wn, bn, Wsn, bsn);

    dim3 grid(NN, BB);
    edge_agg_kernel<<<grid, 256, smem>>>(A, emb_edge, We, be, out);
}

// round 3
// speedup vs baseline: 1.3469x; 1.3469x over previous
#include <cuda_runtime.h>
#include <cuda_bf16.h>
#include <cstdint>

#define BB 8
#define NN 256
#define DD 64
#define ES 72   // E smem row stride (floats): bank = 8g + t, conflict-free
#define WS 72   // WeT smem row stride

__device__ float g_node_x[BB * NN * DD];   // emb_node @ Wn + bn
__device__ float g_sx_relu[BB * NN * DD];  // relu(emb_node @ Wsn + bsn)

// ---------------------------------------------------------------------------
// Kernel A: node GEMMs. One block (64 threads) per (b, j) row.
// ---------------------------------------------------------------------------
__global__ void node_gemm_kernel(const float* __restrict__ emb_node,
                                 const float* __restrict__ Wn,
                                 const float* __restrict__ bn,
                                 const float* __restrict__ Wsn,
                                 const float* __restrict__ bsn) {
    const int r = blockIdx.x;
    const int c = threadIdx.x;
    __shared__ float e[DD];
    e[c] = emb_node[r * DD + c];
    __syncthreads();
    float a1 = bn[c];
    float a2 = bsn[c];
#pragma unroll
    for (int k = 0; k < DD; k++) {
        const float ev = e[k];
        a1 = fmaf(ev, Wn[k * DD + c], a1);
        a2 = fmaf(ev, Wsn[k * DD + c], a2);
    }
    g_node_x[r * DD + c] = a1;
    g_sx_relu[r * DD + c] = fmaxf(a2, 0.0f);
}

// ---------------------------------------------------------------------------
// tf32 helpers
// ---------------------------------------------------------------------------
__device__ __forceinline__ float cvt_tf32(float x) {
    float r;
    asm("cvt.rna.tf32.f32 %0, %1;" : "=f"(r) : "f"(x));
    return r;
}
__device__ __forceinline__ uint32_t fbits(float x) { return __float_as_uint(x); }

__device__ __forceinline__ void mma_tf32(float* c, const uint32_t* a,
                                         uint32_t b0, uint32_t b1) {
    asm volatile(
        "mma.sync.aligned.m16n8k8.row.col.f32.tf32.tf32.f32 "
        "{%0,%1,%2,%3}, {%4,%5,%6,%7}, {%8,%9}, {%0,%1,%2,%3};"
        : "+f"(c[0]), "+f"(c[1]), "+f"(c[2]), "+f"(c[3])
        : "r"(a[0]), "r"(a[1]), "r"(a[2]), "r"(a[3]), "r"(b0), "r"(b1));
}

// ---------------------------------------------------------------------------
// Kernel B: per (b,i). edge_x[256x64] = E @ We via tf32 mma.sync, fused
// relu->edge_out + masked channel-independent aggregation -> node_out.
// 8 warps; warp w owns j-rows [w*32, w*32+32), all 64 cols, K=64.
// Per warp: 2 m-tiles x 8 n-tiles x 8 k-steps of m16n8k8.
// ---------------------------------------------------------------------------
__global__ __launch_bounds__(256, 2)
void edge_mma_kernel(const float* __restrict__ A,
                     const float* __restrict__ emb_edge,
                     const float* __restrict__ We,
                     const float* __restrict__ be,
                     float* __restrict__ out) {
    const int i = blockIdx.x;
    const int b = blockIdx.y;
    const int tid = threadIdx.x;
    const int lane = tid & 31;
    const int warp = tid >> 5;
    const int g = lane >> 2;     // 0..7
    const int t = lane & 3;      // 0..3
    const int jb = warp * 32;
    const int bi = b * NN + i;

    extern __shared__ float sh[];
    float* Esh  = sh;                       // 256*72 = 18432 floats
    float* Wsh  = Esh + NN * ES;            // 64*72  = 4608
    float* Ash  = Wsh + DD * WS;            // 256
    float* red  = Ash + NN;                 // 8*64 = 512

    // ---- stage E (tf32-rounded) ----
    {
        const float4* eg4 = (const float4*)(emb_edge + (size_t)bi * NN * DD);
#pragma unroll
        for (int it = 0; it < 16; it++) {
            const int u = tid + it * 256;       // 0..4095
            const int r = u >> 4, c4 = u & 15;
            float4 v = eg4[u];
            v.x = cvt_tf32(v.x); v.y = cvt_tf32(v.y);
            v.z = cvt_tf32(v.z); v.w = cvt_tf32(v.w);
            *(float4*)&Esh[r * ES + c4 * 4] = v;
        }
        // WeT[n][k] = tf32(We[k][n])
#pragma unroll
        for (int it = 0; it < 16; it++) {
            const int u = tid + it * 256;       // 0..4095
            const int k = u >> 6, n = u & 63;
            Wsh[n * WS + k] = cvt_tf32(We[u]);
        }
        Ash[tid] = A[(size_t)bi * NN + tid];
    }
    __syncthreads();

    // ---- accumulators init with bias (c0/c1 cols nb+2t, nb+2t+1) ----
    float acc[2][8][4];
#pragma unroll
    for (int nt = 0; nt < 8; nt++) {
        const float b0 = be[nt * 8 + 2 * t];
        const float b1 = be[nt * 8 + 2 * t + 1];
#pragma unroll
        for (int mt = 0; mt < 2; mt++) {
            acc[mt][nt][0] = b0; acc[mt][nt][1] = b1;
            acc[mt][nt][2] = b0; acc[mt][nt][3] = b1;
        }
    }

    // ---- main loop over 8 k-steps ----
#pragma unroll
    for (int kb = 0; kb < 8; kb++) {
        const int k0 = kb * 8;
        uint32_t a[2][4];
#pragma unroll
        for (int mt = 0; mt < 2; mt++) {
            const float* base = &Esh[(jb + mt * 16 + g) * ES + k0 + t];
            a[mt][0] = fbits(base[0]);
            a[mt][2] = fbits(base[4]);
            const float* base8 = base + 8 * ES;
            a[mt][1] = fbits(base8[0]);
            a[mt][3] = fbits(base8[4]);
        }
#pragma unroll
        for (int nt = 0; nt < 8; nt++) {
            const float* wb = &Wsh[(nt * 8 + g) * WS + k0 + t];
            const uint32_t b0 = fbits(wb[0]);
            const uint32_t b1 = fbits(wb[4]);
            mma_tf32(acc[0][nt], a[0], b0, b1);
            mma_tf32(acc[1][nt], a[1], b0, b1);
        }
    }

    // ---- epilogue: relu->edge_out, masked aggregation ----
    const float* nx = g_node_x + (size_t)b * NN * DD;
    float* eo = out + BB * NN * DD + (size_t)bi * NN * DD;

    float p[8][2];
#pragma unroll
    for (int nt = 0; nt < 8; nt++) { p[nt][0] = 0.0f; p[nt][1] = 0.0f; }

#pragma unroll
    for (int mt = 0; mt < 2; mt++) {
        const int r0 = jb + mt * 16 + g;
        const int r1 = r0 + 8;
        const float a0 = Ash[r0];
        const float a1 = Ash[r1];
#pragma unroll
        for (int nt = 0; nt < 8; nt++) {
            const int col = nt * 8 + 2 * t;
            const float* c = acc[mt][nt];
            float2 o0 = make_float2(fmaxf(c[0], 0.0f), fmaxf(c[1], 0.0f));
            float2 o1 = make_float2(fmaxf(c[2], 0.0f), fmaxf(c[3], 0.0f));
            *(float2*)&eo[r0 * DD + col] = o0;
            *(float2*)&eo[r1 * DD + col] = o1;
            const float2 n0 = *(const float2*)&nx[r0 * DD + col];
            const float2 n1 = *(const float2*)&nx[r1 * DD + col];
            p[nt][0] = fmaf(a0 * c[0], n0.x, fmaf(a1 * c[2], n1.x, p[nt][0]));
            p[nt][1] = fmaf(a0 * c[1], n0.y, fmaf(a1 * c[3], n1.y, p[nt][1]));
        }
    }

    // reduce over g (lane = g*4 + t)
#pragma unroll
    for (int nt = 0; nt < 8; nt++) {
#pragma unroll
        for (int q = 0; q < 2; q++) {
            float v = p[nt][q];
            v += __shfl_down_sync(0xffffffffu, v, 16);
            v += __shfl_down_sync(0xffffffffu, v, 8);
            v += __shfl_down_sync(0xffffffffu, v, 4);
            p[nt][q] = v;
        }
    }
    if (lane < 4) {
#pragma unroll
        for (int nt = 0; nt < 8; nt++) {
            red[warp * DD + nt * 8 + 2 * t]     = p[nt][0];
            red[warp * DD + nt * 8 + 2 * t + 1] = p[nt][1];
        }
    }
    __syncthreads();

    if (tid < DD) {
        float s = 0.0f;
#pragma unroll
        for (int w = 0; w < 8; w++) s += red[w * DD + tid];
        out[(size_t)bi * DD + tid] = fmaxf(s, 0.0f) + g_sx_relu[(size_t)bi * DD + tid];
    }
}

// ---------------------------------------------------------------------------
// Launch
// ---------------------------------------------------------------------------
extern "C" void kernel_launch(void* const* d_in, const int* in_sizes, int n_in,
                              void* d_out, int out_size) {
    const float* A        = (const float*)d_in[0];
    const float* emb_node = (const float*)d_in[1];
    const float* emb_edge = (const float*)d_in[2];
    const float* Wn       = (const float*)d_in[3];
    const float* bn       = (const float*)d_in[4];
    const float* Wsn      = (const float*)d_in[5];
    const float* bsn      = (const float*)d_in[6];
    const float* We       = (const float*)d_in[7];
    const float* be       = (const float*)d_in[8];
    float* out = (float*)d_out;

    const int smem = (NN * ES + DD * WS + NN + 8 * DD) * sizeof(float); // 95232 B
    cudaFuncSetAttribute(edge_mma_kernel, cudaFuncAttributeMaxDynamicSharedMemorySize, smem);

    node_gemm_kernel<<<BB * NN, DD>>>(emb_node, Wn, bn, Wsn, bsn);

    dim3 grid(NN, BB);
    edge_mma_kernel<<<grid, 256, smem>>>(A, emb_edge, We, be, out);
}

// round 4
// speedup vs baseline: 1.3981x; 1.0380x over previous
#include <cuda_runtime.h>
#include <cuda_bf16.h>
#include <cstdint>

#define BB 8
#define NN 256
#define DD 64

__device__ float g_node_x[BB * NN * DD];   // emb_node @ Wn + bn
__device__ float g_sx_relu[BB * NN * DD];  // relu(emb_node @ Wsn + bsn)

// ---------------------------------------------------------------------------
// Kernel A: node GEMMs. 256 threads, 4 rows per block.
// ---------------------------------------------------------------------------
__global__ __launch_bounds__(256)
void node_gemm_kernel(const float* __restrict__ emb_node,
                      const float* __restrict__ Wn,
                      const float* __restrict__ bn,
                      const float* __restrict__ Wsn,
                      const float* __restrict__ bsn) {
    const int sub = threadIdx.x >> 6;           // 0..3
    const int c = threadIdx.x & 63;
    const int r = blockIdx.x * 4 + sub;
    __shared__ float e[4][DD];
    e[sub][c] = emb_node[r * DD + c];
    __syncthreads();
    float a1 = bn[c];
    float a2 = bsn[c];
#pragma unroll
    for (int k = 0; k < DD; k++) {
        const float ev = e[sub][k];
        a1 = fmaf(ev, Wn[k * DD + c], a1);
        a2 = fmaf(ev, Wsn[k * DD + c], a2);
    }
    g_node_x[r * DD + c] = a1;
    g_sx_relu[r * DD + c] = fmaxf(a2, 0.0f);
}

// ---------------------------------------------------------------------------
// tf32 helpers
// ---------------------------------------------------------------------------
__device__ __forceinline__ float cvt_tf32(float x) {
    float r;
    asm("cvt.rna.tf32.f32 %0, %1;" : "=f"(r) : "f"(x));
    return r;
}
__device__ __forceinline__ uint32_t fbits(float x) { return __float_as_uint(x); }

__device__ __forceinline__ void mma_tf32(float* c, const uint32_t* a,
                                         uint32_t b0, uint32_t b1) {
    asm volatile(
        "mma.sync.aligned.m16n8k8.row.col.f32.tf32.tf32.f32 "
        "{%0,%1,%2,%3}, {%4,%5,%6,%7}, {%8,%9}, {%0,%1,%2,%3};"
        : "+f"(c[0]), "+f"(c[1]), "+f"(c[2]), "+f"(c[3])
        : "r"(a[0]), "r"(a[1]), "r"(a[2]), "r"(a[3]), "r"(b0), "r"(b1));
}

// A-fragment loads straight from GMEM (tf32-rounded in registers).
__device__ __forceinline__ void load_afrag(uint32_t fa[2][4],
                                           const float* __restrict__ E,
                                           int jb, int g, int t, int kb) {
    const int k0 = kb * 8;
#pragma unroll
    for (int mt = 0; mt < 2; mt++) {
        const float* p = E + (jb + mt * 16 + g) * DD + k0 + t;
        fa[mt][0] = fbits(cvt_tf32(__ldg(p)));
        fa[mt][1] = fbits(cvt_tf32(__ldg(p + 8 * DD)));
        fa[mt][2] = fbits(cvt_tf32(__ldg(p + 4)));
        fa[mt][3] = fbits(cvt_tf32(__ldg(p + 8 * DD + 4)));
    }
}

// ---------------------------------------------------------------------------
// Kernel B: per (b,i). edge_x[256x64] = E @ We via tf32 mma.sync, fused
// relu->edge_out + masked channel-independent aggregation -> node_out.
// 8 warps; warp w owns j-rows [w*32, w*32+32). A-frags direct from GMEM
// (double-buffered); W pre-packed in smem in exact B-fragment order.
// ---------------------------------------------------------------------------
__global__ __launch_bounds__(256, 2)
void edge_mma_kernel(const float* __restrict__ A,
                     const float* __restrict__ emb_edge,
                     const float* __restrict__ We,
                     const float* __restrict__ be,
                     float* __restrict__ out) {
    const int i = blockIdx.x;
    const int b = blockIdx.y;
    const int tid = threadIdx.x;
    const int lane = tid & 31;
    const int warp = tid >> 5;
    const int g = lane >> 2;     // 0..7
    const int t = lane & 3;      // 0..3
    const int jb = warp * 32;
    const int bi = b * NN + i;

    __shared__ float2 Wp[64 * 32];   // [(kb*8+nt)*32 + lane] = {WeT[n][k], WeT[n][k+4]}
    __shared__ float Ash[NN];
    __shared__ float red[8 * DD];

    // ---- stage W in fragment order + A row ----
#pragma unroll
    for (int it = 0; it < 8; it++) {
        const int e = tid + it * 256;            // 0..2047
        const int l = e & 31;
        const int nt = (e >> 5) & 7;
        const int kb = e >> 8;
        const int n = nt * 8 + (l >> 2);
        const int k = kb * 8 + (l & 3);
        Wp[e] = make_float2(cvt_tf32(We[k * DD + n]),
                            cvt_tf32(We[(k + 4) * DD + n]));
    }
    Ash[tid] = A[(size_t)bi * NN + tid];
    __syncthreads();

    // ---- accumulators init with bias ----
    float acc[2][8][4];
#pragma unroll
    for (int nt = 0; nt < 8; nt++) {
        const float b0 = be[nt * 8 + 2 * t];
        const float b1 = be[nt * 8 + 2 * t + 1];
#pragma unroll
        for (int mt = 0; mt < 2; mt++) {
            acc[mt][nt][0] = b0; acc[mt][nt][1] = b1;
            acc[mt][nt][2] = b0; acc[mt][nt][3] = b1;
        }
    }

    // ---- main loop: 8 k-steps, A-frags from GMEM, double buffered ----
    const float* E = emb_edge + (size_t)bi * NN * DD;
    uint32_t a[2][4], an[2][4];
    load_afrag(a, E, jb, g, t, 0);
#pragma unroll
    for (int kb = 0; kb < 8; kb++) {
        if (kb < 7) load_afrag(an, E, jb, g, t, kb + 1);
        const float2* wrow = &Wp[kb * 8 * 32 + lane];
#pragma unroll
        for (int nt = 0; nt < 8; nt++) {
            const float2 w = wrow[nt * 32];
            const uint32_t b0 = fbits(w.x);
            const uint32_t b1 = fbits(w.y);
            mma_tf32(acc[0][nt], a[0], b0, b1);
            mma_tf32(acc[1][nt], a[1], b0, b1);
        }
        if (kb < 7) {
#pragma unroll
            for (int mt = 0; mt < 2; mt++)
#pragma unroll
                for (int q = 0; q < 4; q++) a[mt][q] = an[mt][q];
        }
    }

    // ---- epilogue: relu->edge_out, masked aggregation ----
    const float* nx = g_node_x + (size_t)b * NN * DD;
    float* eo = out + BB * NN * DD + (size_t)bi * NN * DD;

    float p[8][2];
#pragma unroll
    for (int nt = 0; nt < 8; nt++) { p[nt][0] = 0.0f; p[nt][1] = 0.0f; }

#pragma unroll
    for (int mt = 0; mt < 2; mt++) {
        const int r0 = jb + mt * 16 + g;
        const int r1 = r0 + 8;
        const float a0 = Ash[r0];
        const float a1 = Ash[r1];
#pragma unroll
        for (int nt = 0; nt < 8; nt++) {
            const int col = nt * 8 + 2 * t;
            const float* c = acc[mt][nt];
            *(float2*)&eo[r0 * DD + col] = make_float2(fmaxf(c[0], 0.0f), fmaxf(c[1], 0.0f));
            *(float2*)&eo[r1 * DD + col] = make_float2(fmaxf(c[2], 0.0f), fmaxf(c[3], 0.0f));
            const float2 n0 = *(const float2*)&nx[r0 * DD + col];
            const float2 n1 = *(const float2*)&nx[r1 * DD + col];
            p[nt][0] = fmaf(a0 * c[0], n0.x, fmaf(a1 * c[2], n1.x, p[nt][0]));
            p[nt][1] = fmaf(a0 * c[1], n0.y, fmaf(a1 * c[3], n1.y, p[nt][1]));
        }
    }

    // reduce over g (lane = g*4 + t)
#pragma unroll
    for (int nt = 0; nt < 8; nt++) {
#pragma unroll
        for (int q = 0; q < 2; q++) {
            float v = p[nt][q];
            v += __shfl_down_sync(0xffffffffu, v, 16);
            v += __shfl_down_sync(0xffffffffu, v, 8);
            v += __shfl_down_sync(0xffffffffu, v, 4);
            p[nt][q] = v;
        }
    }
    if (lane < 4) {
#pragma unroll
        for (int nt = 0; nt < 8; nt++) {
            red[warp * DD + nt * 8 + 2 * t]     = p[nt][0];
            red[warp * DD + nt * 8 + 2 * t + 1] = p[nt][1];
        }
    }
    __syncthreads();

    if (tid < DD) {
        float s = 0.0f;
#pragma unroll
        for (int w = 0; w < 8; w++) s += red[w * DD + tid];
        out[(size_t)bi * DD + tid] = fmaxf(s, 0.0f) + g_sx_relu[(size_t)bi * DD + tid];
    }
}

// ---------------------------------------------------------------------------
// Launch
// ---------------------------------------------------------------------------
extern "C" void kernel_launch(void* const* d_in, const int* in_sizes, int n_in,
                              void* d_out, int out_size) {
    const float* A        = (const float*)d_in[0];
    const float* emb_node = (const float*)d_in[1];
    const float* emb_edge = (const float*)d_in[2];
    const float* Wn       = (const float*)d_in[3];
    const float* bn       = (const float*)d_in[4];
    const float* Wsn      = (const float*)d_in[5];
    const float* bsn      = (const float*)d_in[6];
    const float* We       = (const float*)d_in[7];
    const float* be       = (const float*)d_in[8];
    float* out = (float*)d_out;

    node_gemm_kernel<<<BB * NN / 4, 256>>>(emb_node, Wn, bn, Wsn, bsn);

    dim3 grid(NN, BB);
    edge_mma_kernel<<<grid, 256>>>(A, emb_edge, We, be, out);
}

// round 5
// speedup vs baseline: 1.9412x; 1.3884x over previous
#include <cuda_runtime.h>
#include <cuda_bf16.h>
#include <cstdint>

#define BB 8
#define NN 256
#define DD 64
#define ES 72   // E smem row stride (floats)

__device__ float g_node_x[BB * NN * DD];   // emb_node @ Wn + bn
__device__ float g_sx_relu[BB * NN * DD];  // relu(emb_node @ Wsn + bsn)

// ---------------------------------------------------------------------------
// Kernel A: node GEMMs. 256 threads, 4 rows per block.
// ---------------------------------------------------------------------------
__global__ __launch_bounds__(256)
void node_gemm_kernel(const float* __restrict__ emb_node,
                      const float* __restrict__ Wn,
                      const float* __restrict__ bn,
                      const float* __restrict__ Wsn,
                      const float* __restrict__ bsn) {
    const int sub = threadIdx.x >> 6;
    const int c = threadIdx.x & 63;
    const int r = blockIdx.x * 4 + sub;
    __shared__ float e[4][DD];
    e[sub][c] = emb_node[r * DD + c];
    __syncthreads();
    float a1 = bn[c];
    float a2 = bsn[c];
#pragma unroll
    for (int k = 0; k < DD; k++) {
        const float ev = e[sub][k];
        a1 = fmaf(ev, Wn[k * DD + c], a1);
        a2 = fmaf(ev, Wsn[k * DD + c], a2);
    }
    g_node_x[r * DD + c] = a1;
    g_sx_relu[r * DD + c] = fmaxf(a2, 0.0f);
}

// ---------------------------------------------------------------------------
// helpers
// ---------------------------------------------------------------------------
__device__ __forceinline__ float cvt_tf32(float x) {
    float r;
    asm("cvt.rna.tf32.f32 %0, %1;" : "=f"(r) : "f"(x));
    return r;
}
__device__ __forceinline__ uint32_t fbits(float x) { return __float_as_uint(x); }

__device__ __forceinline__ void mma_tf32(float* c, const uint32_t* a,
                                         uint32_t b0, uint32_t b1) {
    asm volatile(
        "mma.sync.aligned.m16n8k8.row.col.f32.tf32.tf32.f32 "
        "{%0,%1,%2,%3}, {%4,%5,%6,%7}, {%8,%9}, {%0,%1,%2,%3};"
        : "+f"(c[0]), "+f"(c[1]), "+f"(c[2]), "+f"(c[3])
        : "r"(a[0]), "r"(a[1]), "r"(a[2]), "r"(a[3]), "r"(b0), "r"(b1));
}

__device__ __forceinline__ void cp_async16(uint32_t saddr, const void* gptr) {
    asm volatile("cp.async.cg.shared.global [%0], [%1], 16;"
                 :: "r"(saddr), "l"(gptr));
}

// ---------------------------------------------------------------------------
// Kernel B: per (b,i). edge_x[256x64] = E @ We via tf32 mma.sync.
// 8 warps, warp w owns j-rows [w*32, w*32+32).
// E staged by cp.async into pad-72 smem; W fragment-packed float4 (2 k-steps).
// Epilogue: warp scatters raw acc into ITS OWN rows of the (dead) E buffer,
// then coalesced read-back: relu->STG.128 edge_out, coalesced nx loads,
// row-major aggregation, shfl + smem reduce -> node_out.
// ---------------------------------------------------------------------------
__global__ __launch_bounds__(256, 2)
void edge_mma_kernel(const float* __restrict__ A,
                     const float* __restrict__ emb_edge,
                     const float* __restrict__ We,
                     const float* __restrict__ be,
                     float* __restrict__ out) {
    const int i = blockIdx.x;
    const int b = blockIdx.y;
    const int tid = threadIdx.x;
    const int lane = tid & 31;
    const int warp = tid >> 5;
    const int g = lane >> 2;     // 0..7
    const int t = lane & 3;      // 0..3
    const int jb = warp * 32;
    const int bi = b * NN + i;

    extern __shared__ float sh[];
    float*  Esh = sh;                        // 256*72 = 18432 floats (E, then epi tile)
    float4* Wp4 = (float4*)(sh + NN * ES);   // 1024 float4 = 4096 floats
    float*  Ash = sh + NN * ES + 4096;       // 256
    float*  red = Ash + NN;                  // 8*64 = 512

    // ---- stage E via cp.async (raw fp32; tf32 rounding done at frag load) ----
    {
        const float* Eg = emb_edge + (size_t)bi * NN * DD;
        const uint32_t esh_u32 = (uint32_t)__cvta_generic_to_shared(Esh);
#pragma unroll
        for (int it = 0; it < 16; it++) {
            const int chunk = tid + it * 256;          // 0..4095 (16B chunks)
            const int r = chunk >> 4, c16 = chunk & 15;
            cp_async16(esh_u32 + (uint32_t)(r * ES + c16 * 4) * 4u, Eg + chunk * 4);
        }
        asm volatile("cp.async.commit_group;");
    }

    // ---- stage W fragments (float4 = b-frags for 2 consecutive k-steps) ----
    // Wp4[p*256 + nt*32 + l] = {We[k0][n],We[k0+4][n],We[k0+8][n],We[k0+12][n]}
    //   n = nt*8 + (l>>2), k0 = p*16 + (l&3)
#pragma unroll
    for (int it = 0; it < 4; it++) {
        const int e = tid + it * 256;        // 0..1023
        const int p = e >> 8;
        const int nt = (e >> 5) & 7;
        const int l = e & 31;
        const int n = nt * 8 + (l >> 2);
        const int k0 = p * 16 + (l & 3);
        Wp4[e] = make_float4(cvt_tf32(We[k0 * DD + n]),
                             cvt_tf32(We[(k0 + 4) * DD + n]),
                             cvt_tf32(We[(k0 + 8) * DD + n]),
                             cvt_tf32(We[(k0 + 12) * DD + n]));
    }
    Ash[tid] = A[(size_t)bi * NN + tid];

    asm volatile("cp.async.wait_group 0;");
    __syncthreads();

    // ---- accumulators init with bias ----
    float acc[2][8][4];
#pragma unroll
    for (int nt = 0; nt < 8; nt++) {
        const float b0 = be[nt * 8 + 2 * t];
        const float b1 = be[nt * 8 + 2 * t + 1];
#pragma unroll
        for (int mt = 0; mt < 2; mt++) {
            acc[mt][nt][0] = b0; acc[mt][nt][1] = b1;
            acc[mt][nt][2] = b0; acc[mt][nt][3] = b1;
        }
    }

    // ---- main loop: 4 k-step pairs ----
#pragma unroll
    for (int p = 0; p < 4; p++) {
        uint32_t a[2][2][4];   // [kb-in-pair][mt][reg]
#pragma unroll
        for (int kb2 = 0; kb2 < 2; kb2++) {
#pragma unroll
            for (int mt = 0; mt < 2; mt++) {
                const float* base = &Esh[(jb + mt * 16 + g) * ES + p * 16 + kb2 * 8 + t];
                a[kb2][mt][0] = fbits(cvt_tf32(base[0]));
                a[kb2][mt][1] = fbits(cvt_tf32(base[8 * ES]));
                a[kb2][mt][2] = fbits(cvt_tf32(base[4]));
                a[kb2][mt][3] = fbits(cvt_tf32(base[8 * ES + 4]));
            }
        }
        const float4* wrow = &Wp4[p * 256 + lane];
#pragma unroll
        for (int nt = 0; nt < 8; nt++) {
            const float4 w = wrow[nt * 32];
            const uint32_t b0 = fbits(w.x), b1 = fbits(w.y);
            const uint32_t b2 = fbits(w.z), b3 = fbits(w.w);
            mma_tf32(acc[0][nt], a[0][0], b0, b1);
            mma_tf32(acc[1][nt], a[0][1], b0, b1);
            mma_tf32(acc[0][nt], a[1][0], b2, b3);
            mma_tf32(acc[1][nt], a[1][1], b2, b3);
        }
    }

    // ---- epilogue stage 1: scatter raw acc into THIS WARP's rows of Esh ----
    // (warp-local reuse of the dead E tile; no block sync needed)
#pragma unroll
    for (int mt = 0; mt < 2; mt++) {
#pragma unroll
        for (int rh = 0; rh < 2; rh++) {
            const int row = jb + mt * 16 + rh * 8 + g;
#pragma unroll
            for (int nt = 0; nt < 8; nt++) {
                *(float2*)&Esh[row * ES + nt * 8 + 2 * t] =
                    make_float2(acc[mt][nt][rh * 2], acc[mt][nt][rh * 2 + 1]);
            }
        }
    }
    __syncwarp();

    // ---- epilogue stage 2: coalesced read-back, relu->edge_out, aggregation ----
    const float* nx = g_node_x + (size_t)b * NN * DD;
    float* eo = out + BB * NN * DD + (size_t)bi * NN * DD;
    const int lr = lane >> 4;            // 0/1: which of the 2 rows per instr
    const int lc = (lane & 15) * 4;      // column base (float4)

    float p0 = 0.0f, p1 = 0.0f, p2 = 0.0f, p3 = 0.0f;
#pragma unroll
    for (int q = 0; q < 16; q++) {
        const int row = jb + 2 * q + lr;
        const float4 v = *(const float4*)&Esh[row * ES + lc];
        const float av = Ash[row];
        const float4 nv = *(const float4*)&nx[row * DD + lc];
        *(float4*)&eo[row * DD + lc] =
            make_float4(fmaxf(v.x, 0.0f), fmaxf(v.y, 0.0f),
                        fmaxf(v.z, 0.0f), fmaxf(v.w, 0.0f));
        p0 = fmaf(av * v.x, nv.x, p0);
        p1 = fmaf(av * v.y, nv.y, p1);
        p2 = fmaf(av * v.z, nv.z, p2);
        p3 = fmaf(av * v.w, nv.w, p3);
    }
    p0 += __shfl_xor_sync(0xffffffffu, p0, 16);
    p1 += __shfl_xor_sync(0xffffffffu, p1, 16);
    p2 += __shfl_xor_sync(0xffffffffu, p2, 16);
    p3 += __shfl_xor_sync(0xffffffffu, p3, 16);
    if (lane < 16)
        *(float4*)&red[warp * DD + lc] = make_float4(p0, p1, p2, p3);
    __syncthreads();

    if (tid < DD) {
        float s = 0.0f;
#pragma unroll
        for (int w = 0; w < 8; w++) s += red[w * DD + tid];
        out[(size_t)bi * DD + tid] = fmaxf(s, 0.0f) + g_sx_relu[(size_t)bi * DD + tid];
    }
}

// ---------------------------------------------------------------------------
// Launch
// ---------------------------------------------------------------------------
extern "C" void kernel_launch(void* const* d_in, const int* in_sizes, int n_in,
                              void* d_out, int out_size) {
    const float* A        = (const float*)d_in[0];
    const float* emb_node = (const float*)d_in[1];
    const float* emb_edge = (const float*)d_in[2];
    const float* Wn       = (const float*)d_in[3];
    const float* bn       = (const float*)d_in[4];
    const float* Wsn      = (const float*)d_in[5];
    const float* bsn      = (const float*)d_in[6];
    const float* We       = (const float*)d_in[7];
    const float* be       = (const float*)d_in[8];
    float* out = (float*)d_out;

    const int smem = (NN * ES + 4096 + NN + 8 * DD) * sizeof(float); // 93184 B
    cudaFuncSetAttribute(edge_mma_kernel, cudaFuncAttributeMaxDynamicSharedMemorySize, smem);

    node_gemm_kernel<<<BB * NN / 4, 256>>>(emb_node, Wn, bn, Wsn, bsn);

    dim3 grid(NN, BB);
    edge_mma_kernel<<<grid, 256, smem>>>(A, emb_edge, We, be, out);
}

// round 6
// speedup vs baseline: 2.1045x; 1.0841x over previous
#include <cuda_runtime.h>
#include <cuda_bf16.h>
#include <cstdint>

#define BB 8
#define NN 256
#define DD 64
#define ES 72   // E smem row stride (floats), conflict-free fragment LDS

__device__ float g_node_x[BB * NN * DD];   // emb_node @ Wn + bn
__device__ float g_sx_relu[BB * NN * DD];  // relu(emb_node @ Wsn + bsn)
__device__ float4 g_Wpack[1024];           // We fragments, tf32-rounded, b-frag order

// ---------------------------------------------------------------------------
// helpers
// ---------------------------------------------------------------------------
__device__ __forceinline__ float cvt_tf32(float x) {
    float r;
    asm("cvt.rna.tf32.f32 %0, %1;" : "=f"(r) : "f"(x));
    return r;
}
__device__ __forceinline__ uint32_t fbits(float x) { return __float_as_uint(x); }

__device__ __forceinline__ void mma_tf32(float* c, const uint32_t* a,
                                         uint32_t b0, uint32_t b1) {
    asm volatile(
        "mma.sync.aligned.m16n8k8.row.col.f32.tf32.tf32.f32 "
        "{%0,%1,%2,%3}, {%4,%5,%6,%7}, {%8,%9}, {%0,%1,%2,%3};"
        : "+f"(c[0]), "+f"(c[1]), "+f"(c[2]), "+f"(c[3])
        : "r"(a[0]), "r"(a[1]), "r"(a[2]), "r"(a[3]), "r"(b0), "r"(b1));
}

__device__ __forceinline__ void cp_async16(uint32_t saddr, const void* gptr) {
    asm volatile("cp.async.cg.shared.global [%0], [%1], 16;"
                 :: "r"(saddr), "l"(gptr));
}

// ---------------------------------------------------------------------------
// Kernel A: node GEMMs (4 rows / 256-thread block) + W fragment packing
// (block 0 packs We into g_Wpack in tf32 b-fragment order).
// ---------------------------------------------------------------------------
__global__ __launch_bounds__(256)
void node_gemm_kernel(const float* __restrict__ emb_node,
                      const float* __restrict__ Wn,
                      const float* __restrict__ bn,
                      const float* __restrict__ Wsn,
                      const float* __restrict__ bsn,
                      const float* __restrict__ We) {
    if (blockIdx.x == 0) {
#pragma unroll
        for (int it = 0; it < 4; it++) {
            const int e = threadIdx.x + it * 256;   // 0..1023
            const int p = e >> 8;
            const int nt = (e >> 5) & 7;
            const int l = e & 31;
            const int n = nt * 8 + (l >> 2);
            const int k0 = p * 16 + (l & 3);
            g_Wpack[e] = make_float4(cvt_tf32(We[k0 * DD + n]),
                                     cvt_tf32(We[(k0 + 4) * DD + n]),
                                     cvt_tf32(We[(k0 + 8) * DD + n]),
                                     cvt_tf32(We[(k0 + 12) * DD + n]));
        }
    }
    const int sub = threadIdx.x >> 6;
    const int c = threadIdx.x & 63;
    const int r = blockIdx.x * 4 + sub;
    __shared__ float e[4][DD];
    e[sub][c] = emb_node[r * DD + c];
    __syncthreads();
    float a1 = bn[c];
    float a2 = bsn[c];
#pragma unroll
    for (int k = 0; k < DD; k++) {
        const float ev = e[sub][k];
        a1 = fmaf(ev, Wn[k * DD + c], a1);
        a2 = fmaf(ev, Wsn[k * DD + c], a2);
    }
    g_node_x[r * DD + c] = a1;
    g_sx_relu[r * DD + c] = fmaxf(a2, 0.0f);
}

// ---------------------------------------------------------------------------
// Kernel B: per (b,i). edge_x[256x64] = E @ We via tf32 mma.sync.
// 8 warps; warp w fully owns j-rows [w*32, w*32+32):
//  - issues cp.async for its OWN rows, waits its own group (no block barrier)
//  - W b-frags via LDG.128 from g_Wpack (L1-resident, no smem stage)
//  - epilogue in warp-local smem rows; only sync is the final reduce.
// ---------------------------------------------------------------------------
__global__ __launch_bounds__(256, 2)
void edge_mma_kernel(const float* __restrict__ A,
                     const float* __restrict__ emb_edge,
                     const float* __restrict__ be,
                     float* __restrict__ out) {
    const int i = blockIdx.x;
    const int b = blockIdx.y;
    const int tid = threadIdx.x;
    const int lane = tid & 31;
    const int warp = tid >> 5;
    const int g = lane >> 2;     // 0..7
    const int t = lane & 3;      // 0..3
    const int jb = warp * 32;
    const int bi = b * NN + i;

    extern __shared__ float sh[];
    float* Esh = sh;               // 256*72 floats (E, then reused as epi tile)
    float* Ash = sh + NN * ES;     // 256
    float* red = Ash + NN;         // 8*64

    // ---- per-warp E staging via cp.async ----
    {
        const float* Eg = emb_edge + (size_t)bi * NN * DD;
        const uint32_t esh_u32 = (uint32_t)__cvta_generic_to_shared(Esh);
#pragma unroll
        for (int it = 0; it < 16; it++) {
            const int row = jb + it * 2 + (lane >> 4);
            const int c16 = lane & 15;
            cp_async16(esh_u32 + (uint32_t)(row * ES + c16 * 4) * 4u,
                       Eg + row * DD + c16 * 4);
        }
        asm volatile("cp.async.commit_group;");
    }
    Ash[jb + lane] = A[(size_t)bi * NN + jb + lane];

    // ---- accumulators init with bias (while loads are in flight) ----
    float acc[2][8][4];
#pragma unroll
    for (int nt = 0; nt < 8; nt++) {
        const float b0 = __ldg(&be[nt * 8 + 2 * t]);
        const float b1 = __ldg(&be[nt * 8 + 2 * t + 1]);
#pragma unroll
        for (int mt = 0; mt < 2; mt++) {
            acc[mt][nt][0] = b0; acc[mt][nt][1] = b1;
            acc[mt][nt][2] = b0; acc[mt][nt][3] = b1;
        }
    }

    asm volatile("cp.async.wait_group 0;");
    __syncwarp();

    // ---- main loop: 4 k-step pairs ----
#pragma unroll
    for (int p = 0; p < 4; p++) {
        uint32_t a[2][2][4];   // [kb-in-pair][mt][reg]
#pragma unroll
        for (int kb2 = 0; kb2 < 2; kb2++) {
#pragma unroll
            for (int mt = 0; mt < 2; mt++) {
                const float* base = &Esh[(jb + mt * 16 + g) * ES + p * 16 + kb2 * 8 + t];
                a[kb2][mt][0] = fbits(cvt_tf32(base[0]));
                a[kb2][mt][1] = fbits(cvt_tf32(base[8 * ES]));
                a[kb2][mt][2] = fbits(cvt_tf32(base[4]));
                a[kb2][mt][3] = fbits(cvt_tf32(base[8 * ES + 4]));
            }
        }
        const float4* wrow = &g_Wpack[p * 256 + lane];
#pragma unroll
        for (int nt = 0; nt < 8; nt++) {
            const float4 w = __ldg(&wrow[nt * 32]);
            const uint32_t b0 = fbits(w.x), b1 = fbits(w.y);
            const uint32_t b2 = fbits(w.z), b3 = fbits(w.w);
            mma_tf32(acc[0][nt], a[0][0], b0, b1);
            mma_tf32(acc[1][nt], a[0][1], b0, b1);
            mma_tf32(acc[0][nt], a[1][0], b2, b3);
            mma_tf32(acc[1][nt], a[1][1], b2, b3);
        }
    }

    // ---- epilogue stage 1: scatter raw acc into THIS WARP's rows of Esh ----
#pragma unroll
    for (int mt = 0; mt < 2; mt++) {
#pragma unroll
        for (int rh = 0; rh < 2; rh++) {
            const int row = jb + mt * 16 + rh * 8 + g;
#pragma unroll
            for (int nt = 0; nt < 8; nt++) {
                *(float2*)&Esh[row * ES + nt * 8 + 2 * t] =
                    make_float2(acc[mt][nt][rh * 2], acc[mt][nt][rh * 2 + 1]);
            }
        }
    }
    __syncwarp();

    // ---- epilogue stage 2: coalesced read-back, relu->edge_out, aggregation ----
    const float* nx = g_node_x + (size_t)b * NN * DD;
    float* eo = out + BB * NN * DD + (size_t)bi * NN * DD;
    const int lr = lane >> 4;
    const int lc = (lane & 15) * 4;

    float p0 = 0.0f, p1 = 0.0f, p2 = 0.0f, p3 = 0.0f;
#pragma unroll
    for (int q = 0; q < 16; q++) {
        const int row = jb + 2 * q + lr;
        const float4 v = *(const float4*)&Esh[row * ES + lc];
        const float av = Ash[row];
        const float4 nv = *(const float4*)&nx[row * DD + lc];
        *(float4*)&eo[row * DD + lc] =
            make_float4(fmaxf(v.x, 0.0f), fmaxf(v.y, 0.0f),
                        fmaxf(v.z, 0.0f), fmaxf(v.w, 0.0f));
        p0 = fmaf(av * v.x, nv.x, p0);
        p1 = fmaf(av * v.y, nv.y, p1);
        p2 = fmaf(av * v.z, nv.z, p2);
        p3 = fmaf(av * v.w, nv.w, p3);
    }
    p0 += __shfl_xor_sync(0xffffffffu, p0, 16);
    p1 += __shfl_xor_sync(0xffffffffu, p1, 16);
    p2 += __shfl_xor_sync(0xffffffffu, p2, 16);
    p3 += __shfl_xor_sync(0xffffffffu, p3, 16);
    if (lane < 16)
        *(float4*)&red[warp * DD + lc] = make_float4(p0, p1, p2, p3);
    __syncthreads();

    if (tid < DD) {
        float s = 0.0f;
#pragma unroll
        for (int w = 0; w < 8; w++) s += red[w * DD + tid];
        out[(size_t)bi * DD + tid] = fmaxf(s, 0.0f) + g_sx_relu[(size_t)bi * DD + tid];
    }
}

// ---------------------------------------------------------------------------
// Launch
// ---------------------------------------------------------------------------
extern "C" void kernel_launch(void* const* d_in, const int* in_sizes, int n_in,
                              void* d_out, int out_size) {
    const float* A        = (const float*)d_in[0];
    const float* emb_node = (const float*)d_in[1];
    const float* emb_edge = (const float*)d_in[2];
    const float* Wn       = (const float*)d_in[3];
    const float* bn       = (const float*)d_in[4];
    const float* Wsn      = (const float*)d_in[5];
    const float* bsn      = (const float*)d_in[6];
    const float* We       = (const float*)d_in[7];
    const float* be       = (const float*)d_in[8];
    float* out = (float*)d_out;

    const int smem = (NN * ES + NN + 8 * DD) * sizeof(float); // 76800 B
    cudaFuncSetAttribute(edge_mma_kernel, cudaFuncAttributeMaxDynamicSharedMemorySize, smem);

    node_gemm_kernel<<<BB * NN / 4, 256>>>(emb_node, Wn, bn, Wsn, bsn, We);

    dim3 grid(NN, BB);
    edge_mma_kernel<<<grid, 256, smem>>>(A, emb_edge, be, out);
}